// round 6
// baseline (speedup 1.0000x reference)
#include <cuda_runtime.h>
#include <cuda_bf16.h>
#include <math.h>

#define N_NODES 50000
#define N_EDGES 800000
#define NFEAT   128
#define NHID    96
#define NCLASS  40
#define NODE_BLKS 196   // ceil(N_NODES/256)

// ---- static scratch (allocation-free) ----
__device__ __align__(16) float g_h[N_NODES * NHID];   // post-GEMM features
__device__ __align__(16) float g_a[N_NODES * NHID];   // post-aggregation features
__device__ int  g_cnt[N_NODES];     // degree histogram
__device__ int  g_cnt2[N_NODES];    // placement cursors
__device__ int  g_rowbeg[N_NODES];  // CSR segment base (atomic-claimed)
__device__ int  g_cursor;
__device__ __align__(16) int2 g_edges[N_EDGES];   // {src, bits(w)} compact

// ===========================================================================
// CSR build: zero -> hist -> scan+claim -> place
// ===========================================================================
__global__ void zero_cnt_kernel() {
    int i = blockIdx.x * blockDim.x + threadIdx.x;
    if (i < N_NODES) { g_cnt[i] = 0; g_cnt2[i] = 0; }
    if (i == 0) g_cursor = 0;
}

__global__ void hist_kernel(const int* __restrict__ dst) {
    int base = blockIdx.x * 1024 + threadIdx.x;
#pragma unroll
    for (int u = 0; u < 4; u++) {
        int e = base + u * 256;
        if (e < N_EDGES) atomicAdd(&g_cnt[dst[e]], 1);
    }
}

// Block-local inclusive scan; block total claimed from global cursor.
__global__ void scan_claim_kernel() {
    __shared__ int sh[256];
    __shared__ int base_sh;
    int t = threadIdx.x;
    int i = blockIdx.x * 256 + t;
    int c = (i < N_NODES) ? g_cnt[i] : 0;
    sh[t] = c;
    __syncthreads();
#pragma unroll
    for (int off = 1; off < 256; off <<= 1) {
        int v = (t >= off) ? sh[t - off] : 0;
        __syncthreads();
        sh[t] += v;
        __syncthreads();
    }
    if (t == 255) base_sh = atomicAdd(&g_cursor, sh[255]);
    __syncthreads();
    if (i < N_NODES) g_rowbeg[i] = base_sh + sh[t] - c;
}

__global__ void place_kernel(const int* __restrict__ src,
                             const int* __restrict__ dst,
                             const float* __restrict__ ew) {
    int base = blockIdx.x * 1024 + threadIdx.x;
    int   ds[4], ss[4];
    float ws[4];
#pragma unroll
    for (int u = 0; u < 4; u++) {
        int e = base + u * 256;
        bool ok = e < N_EDGES;
        ds[u] = ok ? dst[e] : 0;
        ss[u] = ok ? src[e] : 0;
        ws[u] = ok ? ew[e]  : 0.f;
    }
#pragma unroll
    for (int u = 0; u < 4; u++) {
        int e = base + u * 256;
        if (e < N_EDGES) {
            int p = g_rowbeg[ds[u]] + atomicAdd(&g_cnt2[ds[u]], 1);
            g_edges[p] = make_int2(ss[u], __float_as_int(ws[u]));
        }
    }
}

// ===========================================================================
// GEMM: g_h[r,c] = sum_k X[r,k]*W[k,c]. 8x8 per thread, tile 128x96.
// ===========================================================================
template <int K>
__global__ void gemm_kernel(const float* __restrict__ X,
                            const float* __restrict__ W) {
    __shared__ float Xs[32][132];
    __shared__ float Ws[32][96];
    int tx = threadIdx.x;           // 0..11
    int ty = threadIdx.y;           // 0..15
    int tid = ty * 12 + tx;
    int rowBase = blockIdx.x * 128;

    float acc[8][8] = {};

    for (int kt = 0; kt < K; kt += 32) {
        for (int idx = tid; idx < 128 * 8; idx += 192) {
            int row = idx >> 3;
            int kc  = idx & 7;
            int gr = rowBase + row;
            if (gr >= N_NODES) gr = N_NODES - 1;
            float4 v = *reinterpret_cast<const float4*>(X + (size_t)gr * K + kt + kc * 4);
            Xs[kc * 4 + 0][row] = v.x;
            Xs[kc * 4 + 1][row] = v.y;
            Xs[kc * 4 + 2][row] = v.z;
            Xs[kc * 4 + 3][row] = v.w;
        }
        for (int idx = tid; idx < 32 * 24; idx += 192) {
            int kk = idx / 24;
            int cc = idx % 24;
            *reinterpret_cast<float4*>(&Ws[kk][cc * 4]) =
                *reinterpret_cast<const float4*>(W + (size_t)(kt + kk) * NHID + cc * 4);
        }
        __syncthreads();

#pragma unroll
        for (int k = 0; k < 32; k++) {
            float xr[8], wc[8];
            *reinterpret_cast<float4*>(&xr[0]) = *reinterpret_cast<float4*>(&Xs[k][ty * 8]);
            *reinterpret_cast<float4*>(&xr[4]) = *reinterpret_cast<float4*>(&Xs[k][ty * 8 + 4]);
            *reinterpret_cast<float4*>(&wc[0]) = *reinterpret_cast<float4*>(&Ws[k][tx * 8]);
            *reinterpret_cast<float4*>(&wc[4]) = *reinterpret_cast<float4*>(&Ws[k][tx * 8 + 4]);
#pragma unroll
            for (int i = 0; i < 8; i++)
#pragma unroll
                for (int j = 0; j < 8; j++)
                    acc[i][j] += xr[i] * wc[j];
        }
        __syncthreads();
    }

#pragma unroll
    for (int i = 0; i < 8; i++) {
        int gr = rowBase + ty * 8 + i;
        if (gr < N_NODES) {
            float4 v0 = make_float4(acc[i][0], acc[i][1], acc[i][2], acc[i][3]);
            float4 v1 = make_float4(acc[i][4], acc[i][5], acc[i][6], acc[i][7]);
            float* o = g_h + (size_t)gr * NHID + tx * 8;
            *reinterpret_cast<float4*>(o)     = v0;
            *reinterpret_cast<float4*>(o + 4) = v1;
        }
    }
}

// ===========================================================================
// Aggregation core: warp per node, lane l<24 owns feats [4l,4l+4) (float4).
// 8-edge groups -> 1 LDG.128 per edge per lane; tail predicated with w=0.
// ===========================================================================
__device__ __forceinline__ void agg8(const int2* __restrict__ eb, int j, int cnt,
                                     bool full, int f4, bool act,
                                     float4& acc) {
    int   srcs[8];
    float ws[8];
#pragma unroll
    for (int k = 0; k < 8; k++) {
        bool ok = full || (j + k < cnt);
        int2 e = ok ? __ldg(&eb[j + k]) : make_int2(0, 0);
        srcs[k] = e.x;
        ws[k]   = ok ? __int_as_float(e.y) : 0.f;
    }
    float4 v[8];
#pragma unroll
    for (int k = 0; k < 8; k++) {
        const float4* h = reinterpret_cast<const float4*>(g_h + (size_t)srcs[k] * NHID);
        v[k] = act ? __ldg(h + f4) : make_float4(0.f, 0.f, 0.f, 0.f);
    }
#pragma unroll
    for (int k = 0; k < 8; k++) {
        acc.x += ws[k] * v[k].x;
        acc.y += ws[k] * v[k].y;
        acc.z += ws[k] * v[k].z;
        acc.w += ws[k] * v[k].w;
    }
}

__device__ __forceinline__ void agg_rows(int node, int f4, bool act, float4& acc) {
    int beg = __ldg(&g_rowbeg[node]);
    int cnt = __ldg(&g_cnt[node]);
    const int2* eb = g_edges + beg;
    int nfull = cnt & ~7;
    for (int j = 0; j < nfull; j += 8)
        agg8(eb, j, cnt, true, f4, act, acc);
    if (cnt & 7)
        agg8(eb, nfull, cnt, false, f4, act, acc);
}

// Aggregation + bias + L2-normalize + ReLU. One warp per dst node.
__global__ void agg_kernel(const float* __restrict__ bias) {
    int gw   = (blockIdx.x * blockDim.x + threadIdx.x) >> 5;
    int lane = threadIdx.x & 31;
    if (gw >= N_NODES) return;
    bool act = lane < 24;

    float4 acc = make_float4(0.f, 0.f, 0.f, 0.f);
    agg_rows(gw, lane, act, acc);

    if (act) {
        float4 b = __ldg(reinterpret_cast<const float4*>(bias) + lane);
        acc.x += b.x; acc.y += b.y; acc.z += b.z; acc.w += b.w;
    }
    float s = acc.x * acc.x + acc.y * acc.y + acc.z * acc.z + acc.w * acc.w;
#pragma unroll
    for (int o = 16; o; o >>= 1) s += __shfl_xor_sync(0xFFFFFFFFu, s, o);
    float inv = 1.0f / fmaxf(sqrtf(s), 1e-12f);

    if (act) {
        float4 r = make_float4(fmaxf(acc.x * inv, 0.f), fmaxf(acc.y * inv, 0.f),
                               fmaxf(acc.z * inv, 0.f), fmaxf(acc.w * inv, 0.f));
        reinterpret_cast<float4*>(g_a + (size_t)gw * NHID)[lane] = r;
    }
}

// ===========================================================================
// Layer 3 fused head: agg + bias + norm + relu + emb + logits + softmax.
// ===========================================================================
__global__ void agg_head_kernel(const float* __restrict__ bias,
                                const float* __restrict__ linW,
                                const float* __restrict__ linb,
                                float* __restrict__ out) {
    __shared__ float Ws[NHID * NCLASS];
    __shared__ float bs[NCLASS];
    __shared__ __align__(16) float esh[8][NHID];

    int tid = threadIdx.x;
    for (int i = tid; i < NHID * NCLASS; i += 256) Ws[i] = linW[i];
    if (tid < NCLASS) bs[tid] = linb[tid];
    __syncthreads();

    int wid  = tid >> 5;
    int lane = tid & 31;
    int node = blockIdx.x * 8 + wid;
    if (node >= N_NODES) return;
    bool act = lane < 24;

    float4 acc = make_float4(0.f, 0.f, 0.f, 0.f);
    agg_rows(node, lane, act, acc);

    if (act) {
        float4 b = __ldg(reinterpret_cast<const float4*>(bias) + lane);
        acc.x += b.x; acc.y += b.y; acc.z += b.z; acc.w += b.w;
    }
    float s = acc.x * acc.x + acc.y * acc.y + acc.z * acc.z + acc.w * acc.w;
#pragma unroll
    for (int o = 16; o; o >>= 1) s += __shfl_xor_sync(0xFFFFFFFFu, s, o);
    float inv = 1.0f / fmaxf(sqrtf(s), 1e-12f);

    const size_t EMB_OFF = 0;
    const size_t LOG_OFF = (size_t)N_NODES * NHID;
    const size_t PRB_OFF = LOG_OFF + (size_t)N_NODES * NCLASS;

    if (act) {
        float4 r = make_float4(fmaxf(acc.x * inv, 0.f), fmaxf(acc.y * inv, 0.f),
                               fmaxf(acc.z * inv, 0.f), fmaxf(acc.w * inv, 0.f));
        reinterpret_cast<float4*>(out + EMB_OFF + (size_t)node * NHID)[lane] = r;
        reinterpret_cast<float4*>(&esh[wid][0])[lane] = r;
    }
    __syncwarp();

    float l0 = -INFINITY, l1 = -INFINITY;
    if (lane < NCLASS) {
        float a = bs[lane];
#pragma unroll
        for (int k = 0; k < NHID; k++) a += esh[wid][k] * Ws[k * NCLASS + lane];
        l0 = a;
    }
    if (lane < NCLASS - 32) {
        float a = bs[lane + 32];
#pragma unroll
        for (int k = 0; k < NHID; k++) a += esh[wid][k] * Ws[k * NCLASS + lane + 32];
        l1 = a;
    }

    float m = fmaxf(l0, l1);
#pragma unroll
    for (int o = 16; o; o >>= 1) m = fmaxf(m, __shfl_xor_sync(0xFFFFFFFFu, m, o));
    float sum = 0.f, p0 = 0.f, p1 = 0.f;
    if (lane < NCLASS)      { p0 = expf(l0 - m); sum += p0; }
    if (lane < NCLASS - 32) { p1 = expf(l1 - m); sum += p1; }
#pragma unroll
    for (int o = 16; o; o >>= 1) sum += __shfl_xor_sync(0xFFFFFFFFu, sum, o);
    float invs = 1.0f / sum;

    if (lane < NCLASS) {
        out[LOG_OFF + (size_t)node * NCLASS + lane] = l0;
        out[PRB_OFF + (size_t)node * NCLASS + lane] = p0 * invs;
    }
    if (lane < NCLASS - 32) {
        out[LOG_OFF + (size_t)node * NCLASS + lane + 32] = l1;
        out[PRB_OFF + (size_t)node * NCLASS + lane + 32] = p1 * invs;
    }
}

// ===========================================================================
extern "C" void kernel_launch(void* const* d_in, const int* in_sizes, int n_in,
                              void* d_out, int out_size) {
    const float* x    = (const float*)d_in[0];
    const int*   ei   = (const int*)d_in[1];
    const float* ew   = (const float*)d_in[2];
    const float* W1   = (const float*)d_in[3];
    const float* b1   = (const float*)d_in[4];
    const float* W2   = (const float*)d_in[5];
    const float* b2   = (const float*)d_in[6];
    const float* W3   = (const float*)d_in[7];
    const float* b3   = (const float*)d_in[8];
    const float* linW = (const float*)d_in[9];
    const float* linb = (const float*)d_in[10];
    float* out = (float*)d_out;

    const int* src = ei;
    const int* dst = ei + N_EDGES;

    void* pa = nullptr;
    cudaGetSymbolAddress(&pa, g_a);
    const float* xa = (const float*)pa;

    const int EDGE_GRID4 = (N_EDGES + 1023) / 1024;   // 782 (4 edges/thread)
    const int GEMM_GRID  = (N_NODES + 127) / 128;     // 391
    const int AGG_GRID   = (N_NODES * 32 + 255) / 256;// warp/node, 6250
    dim3 gblk(12, 16);

    // ---- CSR build ----
    zero_cnt_kernel<<<NODE_BLKS, 256>>>();
    hist_kernel<<<EDGE_GRID4, 256>>>(dst);
    scan_claim_kernel<<<NODE_BLKS, 256>>>();
    place_kernel<<<EDGE_GRID4, 256>>>(src, dst, ew);

    // ---- Layer 1 ----
    gemm_kernel<NFEAT><<<GEMM_GRID, gblk>>>(x, W1);
    agg_kernel<<<AGG_GRID, 256>>>(b1);
    // ---- Layer 2 ----
    gemm_kernel<NHID><<<GEMM_GRID, gblk>>>(xa, W2);
    agg_kernel<<<AGG_GRID, 256>>>(b2);
    // ---- Layer 3 + head ----
    gemm_kernel<NHID><<<GEMM_GRID, gblk>>>(xa, W3);
    agg_head_kernel<<<(N_NODES + 7) / 8, 256>>>(b3, linW, linb, out);
}

// round 8
// speedup vs baseline: 1.0491x; 1.0491x over previous
#include <cuda_runtime.h>
#include <cuda_bf16.h>
#include <math.h>

#define N_NODES 50000
#define N_EDGES 800000
#define NFEAT   128
#define NHID    96
#define NCLASS  40
#define NODE_BLKS 196   // ceil(N_NODES/256)

// ---- static scratch (allocation-free) ----
__device__ __align__(16) float g_h[N_NODES * NHID];   // post-GEMM features
__device__ __align__(16) float g_a[N_NODES * NHID];   // post-aggregation features
__device__ int  g_cnt[N_NODES];     // degree histogram
__device__ int  g_cnt2[N_NODES];    // placement cursors
__device__ int  g_rowbeg[N_NODES];  // CSR segment base (atomic-claimed)
__device__ int  g_cursor;
__device__ __align__(16) int2 g_edges[N_EDGES];   // {src, bits(w)} compact

// ===========================================================================
// CSR build: zero -> hist -> scan+claim (1 kernel) -> place
// ===========================================================================
__global__ void zero_cnt_kernel() {
    int i = blockIdx.x * blockDim.x + threadIdx.x;
    if (i < N_NODES) { g_cnt[i] = 0; g_cnt2[i] = 0; }
    if (i == 0) g_cursor = 0;
}

__global__ void hist_kernel(const int* __restrict__ dst) {
    int e = blockIdx.x * blockDim.x + threadIdx.x;
    if (e < N_EDGES) atomicAdd(&g_cnt[dst[e]], 1);
}

// Block-local inclusive scan; block total claimed from global cursor.
__global__ void scan_claim_kernel() {
    __shared__ int sh[256];
    __shared__ int base_sh;
    int t = threadIdx.x;
    int i = blockIdx.x * 256 + t;
    int c = (i < N_NODES) ? g_cnt[i] : 0;
    sh[t] = c;
    __syncthreads();
#pragma unroll
    for (int off = 1; off < 256; off <<= 1) {
        int v = (t >= off) ? sh[t - off] : 0;
        __syncthreads();
        sh[t] += v;
        __syncthreads();
    }
    if (t == 255) base_sh = atomicAdd(&g_cursor, sh[255]);
    __syncthreads();
    if (i < N_NODES) g_rowbeg[i] = base_sh + sh[t] - c;
}

__global__ void place_kernel(const int* __restrict__ src,
                             const int* __restrict__ dst,
                             const float* __restrict__ ew) {
    int e = blockIdx.x * blockDim.x + threadIdx.x;
    if (e >= N_EDGES) return;
    int d = dst[e];
    int p = g_rowbeg[d] + atomicAdd(&g_cnt2[d], 1);
    g_edges[p] = make_int2(src[e], __float_as_int(ew[e]));
}

// ===========================================================================
// GEMM: g_h[r,c] = sum_k X[r,k]*W[k,c]. 8x8 per thread, tile 128x96.
// ===========================================================================
template <int K>
__global__ void gemm_kernel(const float* __restrict__ X,
                            const float* __restrict__ W) {
    __shared__ float Xs[32][132];
    __shared__ float Ws[32][96];
    int tx = threadIdx.x;           // 0..11
    int ty = threadIdx.y;           // 0..15
    int tid = ty * 12 + tx;
    int rowBase = blockIdx.x * 128;

    float acc[8][8] = {};

    for (int kt = 0; kt < K; kt += 32) {
        for (int idx = tid; idx < 128 * 8; idx += 192) {
            int row = idx >> 3;
            int kc  = idx & 7;
            int gr = rowBase + row;
            if (gr >= N_NODES) gr = N_NODES - 1;
            float4 v = *reinterpret_cast<const float4*>(X + (size_t)gr * K + kt + kc * 4);
            Xs[kc * 4 + 0][row] = v.x;
            Xs[kc * 4 + 1][row] = v.y;
            Xs[kc * 4 + 2][row] = v.z;
            Xs[kc * 4 + 3][row] = v.w;
        }
        for (int idx = tid; idx < 32 * 24; idx += 192) {
            int kk = idx / 24;
            int cc = idx % 24;
            *reinterpret_cast<float4*>(&Ws[kk][cc * 4]) =
                *reinterpret_cast<const float4*>(W + (size_t)(kt + kk) * NHID + cc * 4);
        }
        __syncthreads();

#pragma unroll
        for (int k = 0; k < 32; k++) {
            float xr[8], wc[8];
            *reinterpret_cast<float4*>(&xr[0]) = *reinterpret_cast<float4*>(&Xs[k][ty * 8]);
            *reinterpret_cast<float4*>(&xr[4]) = *reinterpret_cast<float4*>(&Xs[k][ty * 8 + 4]);
            *reinterpret_cast<float4*>(&wc[0]) = *reinterpret_cast<float4*>(&Ws[k][tx * 8]);
            *reinterpret_cast<float4*>(&wc[4]) = *reinterpret_cast<float4*>(&Ws[k][tx * 8 + 4]);
#pragma unroll
            for (int i = 0; i < 8; i++)
#pragma unroll
                for (int j = 0; j < 8; j++)
                    acc[i][j] += xr[i] * wc[j];
        }
        __syncthreads();
    }

#pragma unroll
    for (int i = 0; i < 8; i++) {
        int gr = rowBase + ty * 8 + i;
        if (gr < N_NODES) {
            float4 v0 = make_float4(acc[i][0], acc[i][1], acc[i][2], acc[i][3]);
            float4 v1 = make_float4(acc[i][4], acc[i][5], acc[i][6], acc[i][7]);
            float* o = g_h + (size_t)gr * NHID + tx * 8;
            *reinterpret_cast<float4*>(o)     = v0;
            *reinterpret_cast<float4*>(o + 4) = v1;
        }
    }
}

// ===========================================================================
// Aggregation core: warp accumulates weighted rows of g_h for one node.
// 8-edge groups; tail done as one predicated 8-wide group (w=0 lanes).
// ===========================================================================
__device__ __forceinline__ void agg8(const int2* __restrict__ eb, int j, int cnt,
                                     bool full, int lane,
                                     float& a0, float& a1, float& a2) {
    int   srcs[8];
    float ws[8];
#pragma unroll
    for (int k = 0; k < 8; k++) {
        bool ok = full || (j + k < cnt);
        int2 e = ok ? __ldg(&eb[j + k]) : make_int2(0, 0);
        srcs[k] = e.x;
        ws[k]   = ok ? __int_as_float(e.y) : 0.f;
    }
    float v0[8], v1[8], v2[8];
#pragma unroll
    for (int k = 0; k < 8; k++) {
        const float* h = g_h + (size_t)srcs[k] * NHID;
        v0[k] = __ldg(h + lane);
        v1[k] = __ldg(h + lane + 32);
        v2[k] = __ldg(h + lane + 64);
    }
#pragma unroll
    for (int k = 0; k < 8; k++) {
        a0 += ws[k] * v0[k];
        a1 += ws[k] * v1[k];
        a2 += ws[k] * v2[k];
    }
}

__device__ __forceinline__ void agg_rows(int node, int lane,
                                         float& a0, float& a1, float& a2) {
    int beg = __ldg(&g_rowbeg[node]);
    int cnt = __ldg(&g_cnt[node]);
    const int2* eb = g_edges + beg;
    int nfull = cnt & ~7;
    for (int j = 0; j < nfull; j += 8)
        agg8(eb, j, cnt, true, lane, a0, a1, a2);
    if (cnt & 7)
        agg8(eb, nfull, cnt, false, lane, a0, a1, a2);
}

// Aggregation + bias + L2-normalize + ReLU. One warp per dst node.
__global__ void agg_kernel(const float* __restrict__ bias) {
    int gw   = (blockIdx.x * blockDim.x + threadIdx.x) >> 5;
    int lane = threadIdx.x & 31;
    if (gw >= N_NODES) return;

    float a0 = 0.f, a1 = 0.f, a2 = 0.f;
    agg_rows(gw, lane, a0, a1, a2);

    a0 += __ldg(bias + lane); a1 += __ldg(bias + lane + 32); a2 += __ldg(bias + lane + 64);
    float s = a0 * a0 + a1 * a1 + a2 * a2;
#pragma unroll
    for (int o = 16; o; o >>= 1) s += __shfl_xor_sync(0xFFFFFFFFu, s, o);
    float inv = 1.0f / fmaxf(sqrtf(s), 1e-12f);

    float* row = g_a + (size_t)gw * NHID;
    row[lane]      = fmaxf(a0 * inv, 0.f);
    row[lane + 32] = fmaxf(a1 * inv, 0.f);
    row[lane + 64] = fmaxf(a2 * inv, 0.f);
}

// ===========================================================================
// Layer 3 fused head: agg + bias + norm + relu + emb + logits + softmax.
// ===========================================================================
__global__ void agg_head_kernel(const float* __restrict__ bias,
                                const float* __restrict__ linW,
                                const float* __restrict__ linb,
                                float* __restrict__ out) {
    __shared__ float Ws[NHID * NCLASS];
    __shared__ float bs[NCLASS];
    __shared__ float esh[8][NHID];

    int tid = threadIdx.x;
    for (int i = tid; i < NHID * NCLASS; i += 256) Ws[i] = linW[i];
    if (tid < NCLASS) bs[tid] = linb[tid];
    __syncthreads();

    int wid  = tid >> 5;
    int lane = tid & 31;
    int node = blockIdx.x * 8 + wid;
    if (node >= N_NODES) return;

    float a0 = 0.f, a1 = 0.f, a2 = 0.f;
    agg_rows(node, lane, a0, a1, a2);

    a0 += __ldg(bias + lane); a1 += __ldg(bias + lane + 32); a2 += __ldg(bias + lane + 64);
    float s = a0 * a0 + a1 * a1 + a2 * a2;
#pragma unroll
    for (int o = 16; o; o >>= 1) s += __shfl_xor_sync(0xFFFFFFFFu, s, o);
    float inv = 1.0f / fmaxf(sqrtf(s), 1e-12f);
    float e0 = fmaxf(a0 * inv, 0.f);
    float e1 = fmaxf(a1 * inv, 0.f);
    float e2 = fmaxf(a2 * inv, 0.f);

    const size_t EMB_OFF = 0;
    const size_t LOG_OFF = (size_t)N_NODES * NHID;
    const size_t PRB_OFF = LOG_OFF + (size_t)N_NODES * NCLASS;

    out[EMB_OFF + (size_t)node * NHID + lane]      = e0;
    out[EMB_OFF + (size_t)node * NHID + lane + 32] = e1;
    out[EMB_OFF + (size_t)node * NHID + lane + 64] = e2;
    esh[wid][lane] = e0; esh[wid][lane + 32] = e1; esh[wid][lane + 64] = e2;
    __syncwarp();

    float l0 = -INFINITY, l1 = -INFINITY;
    if (lane < NCLASS) {
        float a = bs[lane];
#pragma unroll
        for (int k = 0; k < NHID; k++) a += esh[wid][k] * Ws[k * NCLASS + lane];
        l0 = a;
    }
    if (lane < NCLASS - 32) {
        float a = bs[lane + 32];
#pragma unroll
        for (int k = 0; k < NHID; k++) a += esh[wid][k] * Ws[k * NCLASS + lane + 32];
        l1 = a;
    }

    float m = fmaxf(l0, l1);
#pragma unroll
    for (int o = 16; o; o >>= 1) m = fmaxf(m, __shfl_xor_sync(0xFFFFFFFFu, m, o));
    float sum = 0.f, p0 = 0.f, p1 = 0.f;
    if (lane < NCLASS)      { p0 = expf(l0 - m); sum += p0; }
    if (lane < NCLASS - 32) { p1 = expf(l1 - m); sum += p1; }
#pragma unroll
    for (int o = 16; o; o >>= 1) sum += __shfl_xor_sync(0xFFFFFFFFu, sum, o);
    float invs = 1.0f / sum;

    if (lane < NCLASS) {
        out[LOG_OFF + (size_t)node * NCLASS + lane] = l0;
        out[PRB_OFF + (size_t)node * NCLASS + lane] = p0 * invs;
    }
    if (lane < NCLASS - 32) {
        out[LOG_OFF + (size_t)node * NCLASS + lane + 32] = l1;
        out[PRB_OFF + (size_t)node * NCLASS + lane + 32] = p1 * invs;
    }
}

// ===========================================================================
extern "C" void kernel_launch(void* const* d_in, const int* in_sizes, int n_in,
                              void* d_out, int out_size) {
    const float* x    = (const float*)d_in[0];
    const int*   ei   = (const int*)d_in[1];
    const float* ew   = (const float*)d_in[2];
    const float* W1   = (const float*)d_in[3];
    const float* b1   = (const float*)d_in[4];
    const float* W2   = (const float*)d_in[5];
    const float* b2   = (const float*)d_in[6];
    const float* W3   = (const float*)d_in[7];
    const float* b3   = (const float*)d_in[8];
    const float* linW = (const float*)d_in[9];
    const float* linb = (const float*)d_in[10];
    float* out = (float*)d_out;

    const int* src = ei;
    const int* dst = ei + N_EDGES;

    void* pa = nullptr;
    cudaGetSymbolAddress(&pa, g_a);
    const float* xa = (const float*)pa;

    const int EDGE_GRID = (N_EDGES + 255) / 256;      // 3125
    const int GEMM_GRID = (N_NODES + 127) / 128;      // 391
    const int AGG_GRID  = (N_NODES * 32 + 255) / 256; // warp/node, 6250
    dim3 gblk(12, 16);

    // ---- CSR build, with layer-1 GEMM hoisted to launch slot 3 ----
    // (gemm1 depends only on x/W1; place only needs scan_claim's rowbeg.
    //  Slot 3 is what ncu profiles -> finally measure the GEMM.)
    zero_cnt_kernel<<<NODE_BLKS, 256>>>();                 // slot 0
    hist_kernel<<<EDGE_GRID, 256>>>(dst);                  // slot 1
    scan_claim_kernel<<<NODE_BLKS, 256>>>();               // slot 2
    gemm_kernel<NFEAT><<<GEMM_GRID, gblk>>>(x, W1);        // slot 3 (profiled)
    place_kernel<<<EDGE_GRID, 256>>>(src, dst, ew);        // slot 4

    // ---- Layer 1 aggregation ----
    agg_kernel<<<AGG_GRID, 256>>>(b1);
    // ---- Layer 2 ----
    gemm_kernel<NHID><<<GEMM_GRID, gblk>>>(xa, W2);
    agg_kernel<<<AGG_GRID, 256>>>(b2);
    // ---- Layer 3 + head ----
    gemm_kernel<NHID><<<GEMM_GRID, gblk>>>(xa, W3);
    agg_head_kernel<<<(N_NODES + 7) / 8, 256>>>(b3, linW, linb, out);
}

// round 9
// speedup vs baseline: 1.2069x; 1.1504x over previous
#include <cuda_runtime.h>
#include <cuda_bf16.h>
#include <math.h>

#define N_NODES 50000
#define N_EDGES 800000
#define NFEAT   128
#define NHID    96
#define NCLASS  40
#define NODE_BLKS 196   // ceil(N_NODES/256)

// ---- static scratch (allocation-free) ----
__device__ __align__(16) float g_h[N_NODES * NHID];   // post-GEMM features
__device__ __align__(16) float g_a[N_NODES * NHID];   // post-aggregation features
__device__ int  g_cnt[N_NODES];     // degree histogram
__device__ int  g_cnt2[N_NODES];    // placement cursors
__device__ int  g_rowbeg[N_NODES];  // CSR segment base (atomic-claimed)
__device__ int  g_cursor;
__device__ __align__(16) int2 g_edges[N_EDGES];   // {src, bits(w)} compact

// ===========================================================================
// CSR build: zero -> hist -> scan+claim (1 kernel) -> place
// ===========================================================================
__global__ void zero_cnt_kernel() {
    int i = blockIdx.x * blockDim.x + threadIdx.x;
    if (i < N_NODES) { g_cnt[i] = 0; g_cnt2[i] = 0; }
    if (i == 0) g_cursor = 0;
}

__global__ void hist_kernel(const int* __restrict__ dst) {
    int e = blockIdx.x * blockDim.x + threadIdx.x;
    if (e < N_EDGES) atomicAdd(&g_cnt[dst[e]], 1);
}

// Block-local inclusive scan; block total claimed from global cursor.
__global__ void scan_claim_kernel() {
    __shared__ int sh[256];
    __shared__ int base_sh;
    int t = threadIdx.x;
    int i = blockIdx.x * 256 + t;
    int c = (i < N_NODES) ? g_cnt[i] : 0;
    sh[t] = c;
    __syncthreads();
#pragma unroll
    for (int off = 1; off < 256; off <<= 1) {
        int v = (t >= off) ? sh[t - off] : 0;
        __syncthreads();
        sh[t] += v;
        __syncthreads();
    }
    if (t == 255) base_sh = atomicAdd(&g_cursor, sh[255]);
    __syncthreads();
    if (i < N_NODES) g_rowbeg[i] = base_sh + sh[t] - c;
}

__global__ void place_kernel(const int* __restrict__ src,
                             const int* __restrict__ dst,
                             const float* __restrict__ ew) {
    int e = blockIdx.x * blockDim.x + threadIdx.x;
    if (e >= N_EDGES) return;
    int d = dst[e];
    int p = g_rowbeg[d] + atomicAdd(&g_cnt2[d], 1);
    g_edges[p] = make_int2(src[e], __float_as_int(ew[e]));
}

// ===========================================================================
// GEMM: g_h[r,c] = sum_k X[r,k]*W[k,c]. 8x8 per thread, tile 128x96.
// __launch_bounds__(192, 3): cap regs at 113 so 3 CTAs/SM are resident
// (R8 measured regs=127 -> occ 15.5%, issue 36.5%, fma 24% = occupancy-bound).
// ===========================================================================
template <int K>
__global__ void __launch_bounds__(192, 3) gemm_kernel(const float* __restrict__ X,
                                                      const float* __restrict__ W) {
    __shared__ float Xs[32][132];
    __shared__ float Ws[32][96];
    int tx = threadIdx.x;           // 0..11
    int ty = threadIdx.y;           // 0..15
    int tid = ty * 12 + tx;
    int rowBase = blockIdx.x * 128;

    float acc[8][8] = {};

    for (int kt = 0; kt < K; kt += 32) {
        for (int idx = tid; idx < 128 * 8; idx += 192) {
            int row = idx >> 3;
            int kc  = idx & 7;
            int gr = rowBase + row;
            if (gr >= N_NODES) gr = N_NODES - 1;
            float4 v = *reinterpret_cast<const float4*>(X + (size_t)gr * K + kt + kc * 4);
            Xs[kc * 4 + 0][row] = v.x;
            Xs[kc * 4 + 1][row] = v.y;
            Xs[kc * 4 + 2][row] = v.z;
            Xs[kc * 4 + 3][row] = v.w;
        }
        for (int idx = tid; idx < 32 * 24; idx += 192) {
            int kk = idx / 24;
            int cc = idx % 24;
            *reinterpret_cast<float4*>(&Ws[kk][cc * 4]) =
                *reinterpret_cast<const float4*>(W + (size_t)(kt + kk) * NHID + cc * 4);
        }
        __syncthreads();

#pragma unroll
        for (int k = 0; k < 32; k++) {
            float xr[8], wc[8];
            *reinterpret_cast<float4*>(&xr[0]) = *reinterpret_cast<float4*>(&Xs[k][ty * 8]);
            *reinterpret_cast<float4*>(&xr[4]) = *reinterpret_cast<float4*>(&Xs[k][ty * 8 + 4]);
            *reinterpret_cast<float4*>(&wc[0]) = *reinterpret_cast<float4*>(&Ws[k][tx * 8]);
            *reinterpret_cast<float4*>(&wc[4]) = *reinterpret_cast<float4*>(&Ws[k][tx * 8 + 4]);
#pragma unroll
            for (int i = 0; i < 8; i++)
#pragma unroll
                for (int j = 0; j < 8; j++)
                    acc[i][j] += xr[i] * wc[j];
        }
        __syncthreads();
    }

#pragma unroll
    for (int i = 0; i < 8; i++) {
        int gr = rowBase + ty * 8 + i;
        if (gr < N_NODES) {
            float4 v0 = make_float4(acc[i][0], acc[i][1], acc[i][2], acc[i][3]);
            float4 v1 = make_float4(acc[i][4], acc[i][5], acc[i][6], acc[i][7]);
            float* o = g_h + (size_t)gr * NHID + tx * 8;
            *reinterpret_cast<float4*>(o)     = v0;
            *reinterpret_cast<float4*>(o + 4) = v1;
        }
    }
}

// ===========================================================================
// Aggregation core: warp accumulates weighted rows of g_h for one node.
// 8-edge groups; tail done as one predicated 8-wide group (w=0 lanes).
// ===========================================================================
__device__ __forceinline__ void agg8(const int2* __restrict__ eb, int j, int cnt,
                                     bool full, int lane,
                                     float& a0, float& a1, float& a2) {
    int   srcs[8];
    float ws[8];
#pragma unroll
    for (int k = 0; k < 8; k++) {
        bool ok = full || (j + k < cnt);
        int2 e = ok ? __ldg(&eb[j + k]) : make_int2(0, 0);
        srcs[k] = e.x;
        ws[k]   = ok ? __int_as_float(e.y) : 0.f;
    }
    float v0[8], v1[8], v2[8];
#pragma unroll
    for (int k = 0; k < 8; k++) {
        const float* h = g_h + (size_t)srcs[k] * NHID;
        v0[k] = __ldg(h + lane);
        v1[k] = __ldg(h + lane + 32);
        v2[k] = __ldg(h + lane + 64);
    }
#pragma unroll
    for (int k = 0; k < 8; k++) {
        a0 += ws[k] * v0[k];
        a1 += ws[k] * v1[k];
        a2 += ws[k] * v2[k];
    }
}

__device__ __forceinline__ void agg_rows(int node, int lane,
                                         float& a0, float& a1, float& a2) {
    int beg = __ldg(&g_rowbeg[node]);
    int cnt = __ldg(&g_cnt[node]);
    const int2* eb = g_edges + beg;
    int nfull = cnt & ~7;
    for (int j = 0; j < nfull; j += 8)
        agg8(eb, j, cnt, true, lane, a0, a1, a2);
    if (cnt & 7)
        agg8(eb, nfull, cnt, false, lane, a0, a1, a2);
}

// Aggregation + bias + L2-normalize + ReLU. One warp per dst node.
__global__ void agg_kernel(const float* __restrict__ bias) {
    int gw   = (blockIdx.x * blockDim.x + threadIdx.x) >> 5;
    int lane = threadIdx.x & 31;
    if (gw >= N_NODES) return;

    float a0 = 0.f, a1 = 0.f, a2 = 0.f;
    agg_rows(gw, lane, a0, a1, a2);

    a0 += __ldg(bias + lane); a1 += __ldg(bias + lane + 32); a2 += __ldg(bias + lane + 64);
    float s = a0 * a0 + a1 * a1 + a2 * a2;
#pragma unroll
    for (int o = 16; o; o >>= 1) s += __shfl_xor_sync(0xFFFFFFFFu, s, o);
    float inv = 1.0f / fmaxf(sqrtf(s), 1e-12f);

    float* row = g_a + (size_t)gw * NHID;
    row[lane]      = fmaxf(a0 * inv, 0.f);
    row[lane + 32] = fmaxf(a1 * inv, 0.f);
    row[lane + 64] = fmaxf(a2 * inv, 0.f);
}

// ===========================================================================
// Layer 3 fused head: agg + bias + norm + relu + emb + logits + softmax.
// ===========================================================================
__global__ void agg_head_kernel(const float* __restrict__ bias,
                                const float* __restrict__ linW,
                                const float* __restrict__ linb,
                                float* __restrict__ out) {
    __shared__ float Ws[NHID * NCLASS];
    __shared__ float bs[NCLASS];
    __shared__ float esh[8][NHID];

    int tid = threadIdx.x;
    for (int i = tid; i < NHID * NCLASS; i += 256) Ws[i] = linW[i];
    if (tid < NCLASS) bs[tid] = linb[tid];
    __syncthreads();

    int wid  = tid >> 5;
    int lane = tid & 31;
    int node = blockIdx.x * 8 + wid;
    if (node >= N_NODES) return;

    float a0 = 0.f, a1 = 0.f, a2 = 0.f;
    agg_rows(node, lane, a0, a1, a2);

    a0 += __ldg(bias + lane); a1 += __ldg(bias + lane + 32); a2 += __ldg(bias + lane + 64);
    float s = a0 * a0 + a1 * a1 + a2 * a2;
#pragma unroll
    for (int o = 16; o; o >>= 1) s += __shfl_xor_sync(0xFFFFFFFFu, s, o);
    float inv = 1.0f / fmaxf(sqrtf(s), 1e-12f);
    float e0 = fmaxf(a0 * inv, 0.f);
    float e1 = fmaxf(a1 * inv, 0.f);
    float e2 = fmaxf(a2 * inv, 0.f);

    const size_t EMB_OFF = 0;
    const size_t LOG_OFF = (size_t)N_NODES * NHID;
    const size_t PRB_OFF = LOG_OFF + (size_t)N_NODES * NCLASS;

    out[EMB_OFF + (size_t)node * NHID + lane]      = e0;
    out[EMB_OFF + (size_t)node * NHID + lane + 32] = e1;
    out[EMB_OFF + (size_t)node * NHID + lane + 64] = e2;
    esh[wid][lane] = e0; esh[wid][lane + 32] = e1; esh[wid][lane + 64] = e2;
    __syncwarp();

    float l0 = -INFINITY, l1 = -INFINITY;
    if (lane < NCLASS) {
        float a = bs[lane];
#pragma unroll
        for (int k = 0; k < NHID; k++) a += esh[wid][k] * Ws[k * NCLASS + lane];
        l0 = a;
    }
    if (lane < NCLASS - 32) {
        float a = bs[lane + 32];
#pragma unroll
        for (int k = 0; k < NHID; k++) a += esh[wid][k] * Ws[k * NCLASS + lane + 32];
        l1 = a;
    }

    float m = fmaxf(l0, l1);
#pragma unroll
    for (int o = 16; o; o >>= 1) m = fmaxf(m, __shfl_xor_sync(0xFFFFFFFFu, m, o));
    float sum = 0.f, p0 = 0.f, p1 = 0.f;
    if (lane < NCLASS)      { p0 = expf(l0 - m); sum += p0; }
    if (lane < NCLASS - 32) { p1 = expf(l1 - m); sum += p1; }
#pragma unroll
    for (int o = 16; o; o >>= 1) sum += __shfl_xor_sync(0xFFFFFFFFu, sum, o);
    float invs = 1.0f / sum;

    if (lane < NCLASS) {
        out[LOG_OFF + (size_t)node * NCLASS + lane] = l0;
        out[PRB_OFF + (size_t)node * NCLASS + lane] = p0 * invs;
    }
    if (lane < NCLASS - 32) {
        out[LOG_OFF + (size_t)node * NCLASS + lane + 32] = l1;
        out[PRB_OFF + (size_t)node * NCLASS + lane + 32] = p1 * invs;
    }
}

// ===========================================================================
extern "C" void kernel_launch(void* const* d_in, const int* in_sizes, int n_in,
                              void* d_out, int out_size) {
    const float* x    = (const float*)d_in[0];
    const int*   ei   = (const int*)d_in[1];
    const float* ew   = (const float*)d_in[2];
    const float* W1   = (const float*)d_in[3];
    const float* b1   = (const float*)d_in[4];
    const float* W2   = (const float*)d_in[5];
    const float* b2   = (const float*)d_in[6];
    const float* W3   = (const float*)d_in[7];
    const float* b3   = (const float*)d_in[8];
    const float* linW = (const float*)d_in[9];
    const float* linb = (const float*)d_in[10];
    float* out = (float*)d_out;

    const int* src = ei;
    const int* dst = ei + N_EDGES;

    void* pa = nullptr;
    cudaGetSymbolAddress(&pa, g_a);
    const float* xa = (const float*)pa;

    const int EDGE_GRID = (N_EDGES + 255) / 256;      // 3125
    const int GEMM_GRID = (N_NODES + 127) / 128;      // 391
    const int AGG_GRID  = (N_NODES * 32 + 255) / 256; // warp/node, 6250
    dim3 gblk(12, 16);

    // ---- CSR build, layer-1 GEMM kept in slot 3 (profiled) ----
    zero_cnt_kernel<<<NODE_BLKS, 256>>>();                 // slot 0
    hist_kernel<<<EDGE_GRID, 256>>>(dst);                  // slot 1
    scan_claim_kernel<<<NODE_BLKS, 256>>>();               // slot 2
    gemm_kernel<NFEAT><<<GEMM_GRID, gblk>>>(x, W1);        // slot 3 (profiled)
    place_kernel<<<EDGE_GRID, 256>>>(src, dst, ew);        // slot 4

    // ---- Layer 1 aggregation ----
    agg_kernel<<<AGG_GRID, 256>>>(b1);
    // ---- Layer 2 ----
    gemm_kernel<NHID><<<GEMM_GRID, gblk>>>(xa, W2);
    agg_kernel<<<AGG_GRID, 256>>>(b2);
    // ---- Layer 3 + head ----
    gemm_kernel<NHID><<<GEMM_GRID, gblk>>>(xa, W3);
    agg_head_kernel<<<(N_NODES + 7) / 8, 256>>>(b3, linW, linb, out);
}

// round 10
// speedup vs baseline: 1.2171x; 1.0084x over previous
#include <cuda_runtime.h>
#include <cuda_bf16.h>
#include <math.h>

#define N_NODES 50000
#define N_EDGES 800000
#define NFEAT   128
#define NHID    96
#define NCLASS  40
#define NODE_BLKS 196   // ceil(N_NODES/256)

// ---- static scratch (allocation-free) ----
__device__ __align__(16) float g_h[N_NODES * NHID];   // post-GEMM features
__device__ __align__(16) float g_a[N_NODES * NHID];   // post-aggregation features
__device__ int  g_cnt[N_NODES];     // degree histogram
__device__ int  g_cnt2[N_NODES];    // placement cursors
__device__ int  g_rowbeg[N_NODES];  // CSR segment base (atomic-claimed)
__device__ int  g_cursor;
__device__ __align__(16) int2 g_edges[N_EDGES];   // {src, bits(w)} compact

// ===========================================================================
// CSR build: zero -> hist -> scan+claim (1 kernel) -> place
// ===========================================================================
__global__ void zero_cnt_kernel() {
    int i = blockIdx.x * blockDim.x + threadIdx.x;
    if (i < N_NODES) { g_cnt[i] = 0; g_cnt2[i] = 0; }
    if (i == 0) g_cursor = 0;
}

__global__ void hist_kernel(const int* __restrict__ dst) {
    int e = blockIdx.x * blockDim.x + threadIdx.x;
    if (e < N_EDGES) atomicAdd(&g_cnt[dst[e]], 1);
}

// Block-local inclusive scan; block total claimed from global cursor.
__global__ void scan_claim_kernel() {
    __shared__ int sh[256];
    __shared__ int base_sh;
    int t = threadIdx.x;
    int i = blockIdx.x * 256 + t;
    int c = (i < N_NODES) ? g_cnt[i] : 0;
    sh[t] = c;
    __syncthreads();
#pragma unroll
    for (int off = 1; off < 256; off <<= 1) {
        int v = (t >= off) ? sh[t - off] : 0;
        __syncthreads();
        sh[t] += v;
        __syncthreads();
    }
    if (t == 255) base_sh = atomicAdd(&g_cursor, sh[255]);
    __syncthreads();
    if (i < N_NODES) g_rowbeg[i] = base_sh + sh[t] - c;
}

__global__ void place_kernel(const int* __restrict__ src,
                             const int* __restrict__ dst,
                             const float* __restrict__ ew) {
    int e = blockIdx.x * blockDim.x + threadIdx.x;
    if (e >= N_EDGES) return;
    int d = dst[e];
    int p = g_rowbeg[d] + atomicAdd(&g_cnt2[d], 1);
    g_edges[p] = make_int2(src[e], __float_as_int(ew[e]));
}

// ===========================================================================
// GEMM: g_h[r,c] = sum_k X[r,k]*W[k,c]. 8x8 per thread, tile 128x96.
// Inner product uses packed fma.rn.f32x2 (sm_100+): 2 FLOP per issued
// instruction -> halves FFMA issue pressure (R9: issue 49.9%, fma 34.2%,
// scalar-FFMA issue budget was the roof). Rounding per element is rn,
// identical to scalar FFMA.
// ===========================================================================
template <int K>
__global__ void __launch_bounds__(192, 3) gemm_kernel(const float* __restrict__ X,
                                                      const float* __restrict__ W) {
    __shared__ float Xs[32][132];
    __shared__ float Ws[32][96];
    int tx = threadIdx.x;           // 0..11 -> cols tx*8..tx*8+7
    int ty = threadIdx.y;           // 0..15 -> rows ty*8..ty*8+7
    int tid = ty * 12 + tx;
    int rowBase = blockIdx.x * 128;

    // acc2[i][p] holds packed {col 2p, col 2p+1} for row i (f32x2)
    unsigned long long acc2[8][4] = {};

    for (int kt = 0; kt < K; kt += 32) {
        for (int idx = tid; idx < 128 * 8; idx += 192) {
            int row = idx >> 3;
            int kc  = idx & 7;
            int gr = rowBase + row;
            if (gr >= N_NODES) gr = N_NODES - 1;
            float4 v = *reinterpret_cast<const float4*>(X + (size_t)gr * K + kt + kc * 4);
            Xs[kc * 4 + 0][row] = v.x;
            Xs[kc * 4 + 1][row] = v.y;
            Xs[kc * 4 + 2][row] = v.z;
            Xs[kc * 4 + 3][row] = v.w;
        }
        for (int idx = tid; idx < 32 * 24; idx += 192) {
            int kk = idx / 24;
            int cc = idx % 24;
            *reinterpret_cast<float4*>(&Ws[kk][cc * 4]) =
                *reinterpret_cast<const float4*>(W + (size_t)(kt + kk) * NHID + cc * 4);
        }
        __syncthreads();

#pragma unroll
        for (int k = 0; k < 32; k++) {
            float xr[8];
            *reinterpret_cast<float4*>(&xr[0]) = *reinterpret_cast<float4*>(&Xs[k][ty * 8]);
            *reinterpret_cast<float4*>(&xr[4]) = *reinterpret_cast<float4*>(&Xs[k][ty * 8 + 4]);
            // 8 weight cols as 4 packed f32x2 (16B-aligned: 96-f rows, 32B col offset)
            ulonglong2 wA = *reinterpret_cast<ulonglong2*>(&Ws[k][tx * 8]);
            ulonglong2 wB = *reinterpret_cast<ulonglong2*>(&Ws[k][tx * 8 + 4]);
            unsigned long long wc2[4] = {wA.x, wA.y, wB.x, wB.y};
#pragma unroll
            for (int i = 0; i < 8; i++) {
                unsigned int xb = __float_as_uint(xr[i]);
                unsigned long long xs;
                asm("mov.b64 %0, {%1, %1};" : "=l"(xs) : "r"(xb));
#pragma unroll
                for (int p = 0; p < 4; p++)
                    asm("fma.rn.f32x2 %0, %1, %2, %0;"
                        : "+l"(acc2[i][p]) : "l"(xs), "l"(wc2[p]));
            }
        }
        __syncthreads();
    }

#pragma unroll
    for (int i = 0; i < 8; i++) {
        int gr = rowBase + ty * 8 + i;
        if (gr < N_NODES) {
            // acc2[i] in memory is exactly cols 0..7 as 8 floats (lo half = even col)
            const float* af = reinterpret_cast<const float*>(&acc2[i][0]);
            float4 v0 = make_float4(af[0], af[1], af[2], af[3]);
            float4 v1 = make_float4(af[4], af[5], af[6], af[7]);
            float* o = g_h + (size_t)gr * NHID + tx * 8;
            *reinterpret_cast<float4*>(o)     = v0;
            *reinterpret_cast<float4*>(o + 4) = v1;
        }
    }
}

// ===========================================================================
// Aggregation core: warp accumulates weighted rows of g_h for one node.
// 8-edge groups; tail done as one predicated 8-wide group (w=0 lanes).
// ===========================================================================
__device__ __forceinline__ void agg8(const int2* __restrict__ eb, int j, int cnt,
                                     bool full, int lane,
                                     float& a0, float& a1, float& a2) {
    int   srcs[8];
    float ws[8];
#pragma unroll
    for (int k = 0; k < 8; k++) {
        bool ok = full || (j + k < cnt);
        int2 e = ok ? __ldg(&eb[j + k]) : make_int2(0, 0);
        srcs[k] = e.x;
        ws[k]   = ok ? __int_as_float(e.y) : 0.f;
    }
    float v0[8], v1[8], v2[8];
#pragma unroll
    for (int k = 0; k < 8; k++) {
        const float* h = g_h + (size_t)srcs[k] * NHID;
        v0[k] = __ldg(h + lane);
        v1[k] = __ldg(h + lane + 32);
        v2[k] = __ldg(h + lane + 64);
    }
#pragma unroll
    for (int k = 0; k < 8; k++) {
        a0 += ws[k] * v0[k];
        a1 += ws[k] * v1[k];
        a2 += ws[k] * v2[k];
    }
}

__device__ __forceinline__ void agg_rows(int node, int lane,
                                         float& a0, float& a1, float& a2) {
    int beg = __ldg(&g_rowbeg[node]);
    int cnt = __ldg(&g_cnt[node]);
    const int2* eb = g_edges + beg;
    int nfull = cnt & ~7;
    for (int j = 0; j < nfull; j += 8)
        agg8(eb, j, cnt, true, lane, a0, a1, a2);
    if (cnt & 7)
        agg8(eb, nfull, cnt, false, lane, a0, a1, a2);
}

// Aggregation + bias + L2-normalize + ReLU. One warp per dst node.
__global__ void agg_kernel(const float* __restrict__ bias) {
    int gw   = (blockIdx.x * blockDim.x + threadIdx.x) >> 5;
    int lane = threadIdx.x & 31;
    if (gw >= N_NODES) return;

    float a0 = 0.f, a1 = 0.f, a2 = 0.f;
    agg_rows(gw, lane, a0, a1, a2);

    a0 += __ldg(bias + lane); a1 += __ldg(bias + lane + 32); a2 += __ldg(bias + lane + 64);
    float s = a0 * a0 + a1 * a1 + a2 * a2;
#pragma unroll
    for (int o = 16; o; o >>= 1) s += __shfl_xor_sync(0xFFFFFFFFu, s, o);
    float inv = 1.0f / fmaxf(sqrtf(s), 1e-12f);

    float* row = g_a + (size_t)gw * NHID;
    row[lane]      = fmaxf(a0 * inv, 0.f);
    row[lane + 32] = fmaxf(a1 * inv, 0.f);
    row[lane + 64] = fmaxf(a2 * inv, 0.f);
}

// ===========================================================================
// Layer 3 fused head: agg + bias + norm + relu + emb + logits + softmax.
// ===========================================================================
__global__ void agg_head_kernel(const float* __restrict__ bias,
                                const float* __restrict__ linW,
                                const float* __restrict__ linb,
                                float* __restrict__ out) {
    __shared__ float Ws[NHID * NCLASS];
    __shared__ float bs[NCLASS];
    __shared__ float esh[8][NHID];

    int tid = threadIdx.x;
    for (int i = tid; i < NHID * NCLASS; i += 256) Ws[i] = linW[i];
    if (tid < NCLASS) bs[tid] = linb[tid];
    __syncthreads();

    int wid  = tid >> 5;
    int lane = tid & 31;
    int node = blockIdx.x * 8 + wid;
    if (node >= N_NODES) return;

    float a0 = 0.f, a1 = 0.f, a2 = 0.f;
    agg_rows(node, lane, a0, a1, a2);

    a0 += __ldg(bias + lane); a1 += __ldg(bias + lane + 32); a2 += __ldg(bias + lane + 64);
    float s = a0 * a0 + a1 * a1 + a2 * a2;
#pragma unroll
    for (int o = 16; o; o >>= 1) s += __shfl_xor_sync(0xFFFFFFFFu, s, o);
    float inv = 1.0f / fmaxf(sqrtf(s), 1e-12f);
    float e0 = fmaxf(a0 * inv, 0.f);
    float e1 = fmaxf(a1 * inv, 0.f);
    float e2 = fmaxf(a2 * inv, 0.f);

    const size_t EMB_OFF = 0;
    const size_t LOG_OFF = (size_t)N_NODES * NHID;
    const size_t PRB_OFF = LOG_OFF + (size_t)N_NODES * NCLASS;

    out[EMB_OFF + (size_t)node * NHID + lane]      = e0;
    out[EMB_OFF + (size_t)node * NHID + lane + 32] = e1;
    out[EMB_OFF + (size_t)node * NHID + lane + 64] = e2;
    esh[wid][lane] = e0; esh[wid][lane + 32] = e1; esh[wid][lane + 64] = e2;
    __syncwarp();

    float l0 = -INFINITY, l1 = -INFINITY;
    if (lane < NCLASS) {
        float a = bs[lane];
#pragma unroll
        for (int k = 0; k < NHID; k++) a += esh[wid][k] * Ws[k * NCLASS + lane];
        l0 = a;
    }
    if (lane < NCLASS - 32) {
        float a = bs[lane + 32];
#pragma unroll
        for (int k = 0; k < NHID; k++) a += esh[wid][k] * Ws[k * NCLASS + lane + 32];
        l1 = a;
    }

    float m = fmaxf(l0, l1);
#pragma unroll
    for (int o = 16; o; o >>= 1) m = fmaxf(m, __shfl_xor_sync(0xFFFFFFFFu, m, o));
    float sum = 0.f, p0 = 0.f, p1 = 0.f;
    if (lane < NCLASS)      { p0 = expf(l0 - m); sum += p0; }
    if (lane < NCLASS - 32) { p1 = expf(l1 - m); sum += p1; }
#pragma unroll
    for (int o = 16; o; o >>= 1) sum += __shfl_xor_sync(0xFFFFFFFFu, sum, o);
    float invs = 1.0f / sum;

    if (lane < NCLASS) {
        out[LOG_OFF + (size_t)node * NCLASS + lane] = l0;
        out[PRB_OFF + (size_t)node * NCLASS + lane] = p0 * invs;
    }
    if (lane < NCLASS - 32) {
        out[LOG_OFF + (size_t)node * NCLASS + lane + 32] = l1;
        out[PRB_OFF + (size_t)node * NCLASS + lane + 32] = p1 * invs;
    }
}

// ===========================================================================
extern "C" void kernel_launch(void* const* d_in, const int* in_sizes, int n_in,
                              void* d_out, int out_size) {
    const float* x    = (const float*)d_in[0];
    const int*   ei   = (const int*)d_in[1];
    const float* ew   = (const float*)d_in[2];
    const float* W1   = (const float*)d_in[3];
    const float* b1   = (const float*)d_in[4];
    const float* W2   = (const float*)d_in[5];
    const float* b2   = (const float*)d_in[6];
    const float* W3   = (const float*)d_in[7];
    const float* b3   = (const float*)d_in[8];
    const float* linW = (const float*)d_in[9];
    const float* linb = (const float*)d_in[10];
    float* out = (float*)d_out;

    const int* src = ei;
    const int* dst = ei + N_EDGES;

    void* pa = nullptr;
    cudaGetSymbolAddress(&pa, g_a);
    const float* xa = (const float*)pa;

    const int EDGE_GRID = (N_EDGES + 255) / 256;      // 3125
    const int GEMM_GRID = (N_NODES + 127) / 128;      // 391
    const int AGG_GRID  = (N_NODES * 32 + 255) / 256; // warp/node, 6250
    dim3 gblk(12, 16);

    // ---- CSR build, layer-1 GEMM kept in slot 3 (profiled) ----
    zero_cnt_kernel<<<NODE_BLKS, 256>>>();                 // slot 0
    hist_kernel<<<EDGE_GRID, 256>>>(dst);                  // slot 1
    scan_claim_kernel<<<NODE_BLKS, 256>>>();               // slot 2
    gemm_kernel<NFEAT><<<GEMM_GRID, gblk>>>(x, W1);        // slot 3 (profiled)
    place_kernel<<<EDGE_GRID, 256>>>(src, dst, ew);        // slot 4

    // ---- Layer 1 aggregation ----
    agg_kernel<<<AGG_GRID, 256>>>(b1);
    // ---- Layer 2 ----
    gemm_kernel<NHID><<<GEMM_GRID, gblk>>>(xa, W2);
    agg_kernel<<<AGG_GRID, 256>>>(b2);
    // ---- Layer 3 + head ----
    gemm_kernel<NHID><<<GEMM_GRID, gblk>>>(xa, W3);
    agg_head_kernel<<<(N_NODES + 7) / 8, 256>>>(b3, linW, linb, out);
}

// round 11
// speedup vs baseline: 1.2561x; 1.0320x over previous
#include <cuda_runtime.h>
#include <cuda_bf16.h>
#include <math.h>

#define N_NODES 50000
#define N_EDGES 800000
#define NFEAT   128
#define NHID    96
#define NCLASS  40
#define NODE_BLKS 196   // ceil(N_NODES/256)

// ---- static scratch (allocation-free) ----
__device__ __align__(16) float g_h[N_NODES * NHID];   // post-GEMM features
__device__ __align__(16) float g_a[N_NODES * NHID];   // post-aggregation features
__device__ int  g_cnt[N_NODES];     // degree histogram
__device__ int  g_cnt2[N_NODES];    // placement cursors
__device__ int  g_rowbeg[N_NODES];  // CSR segment base (atomic-claimed)
__device__ int  g_cursor;
__device__ __align__(16) int2 g_edges[N_EDGES];   // {src, bits(w)} compact

// ===========================================================================
// CSR build: zero -> hist -> scan+claim (1 kernel) -> place
// ===========================================================================
__global__ void zero_cnt_kernel() {
    int i = blockIdx.x * blockDim.x + threadIdx.x;
    if (i < N_NODES) { g_cnt[i] = 0; g_cnt2[i] = 0; }
    if (i == 0) g_cursor = 0;
}

__global__ void hist_kernel(const int* __restrict__ dst) {
    int e = blockIdx.x * blockDim.x + threadIdx.x;
    if (e < N_EDGES) atomicAdd(&g_cnt[dst[e]], 1);
}

// Block-local inclusive scan; block total claimed from global cursor.
__global__ void scan_claim_kernel() {
    __shared__ int sh[256];
    __shared__ int base_sh;
    int t = threadIdx.x;
    int i = blockIdx.x * 256 + t;
    int c = (i < N_NODES) ? g_cnt[i] : 0;
    sh[t] = c;
    __syncthreads();
#pragma unroll
    for (int off = 1; off < 256; off <<= 1) {
        int v = (t >= off) ? sh[t - off] : 0;
        __syncthreads();
        sh[t] += v;
        __syncthreads();
    }
    if (t == 255) base_sh = atomicAdd(&g_cursor, sh[255]);
    __syncthreads();
    if (i < N_NODES) g_rowbeg[i] = base_sh + sh[t] - c;
}

__global__ void place_kernel(const int* __restrict__ src,
                             const int* __restrict__ dst,
                             const float* __restrict__ ew) {
    int e = blockIdx.x * blockDim.x + threadIdx.x;
    if (e >= N_EDGES) return;
    int d = dst[e];
    int p = g_rowbeg[d] + atomicAdd(&g_cnt2[d], 1);
    g_edges[p] = make_int2(src[e], __float_as_int(ew[e]));
}

// ===========================================================================
// GEMM: g_h[r,c] = sum_k X[r,k]*W[k,c]. CTA tile 128x96, 256 threads (16x16),
// per-thread tile 8 rows x 6 cols (24 f32x2 accumulators).
// R10 showed the GEMM is LDS-latency bound (issue halved, dur unchanged,
// L1 56%, occ 23.5%) -> this config raises occupancy to 24 warps/SM (37.5%).
// ===========================================================================
template <int K>
__global__ void __launch_bounds__(256, 3) gemm_kernel(const float* __restrict__ X,
                                                      const float* __restrict__ W) {
    __shared__ float Xs[32][132];   // [k][row], padded
    __shared__ float Ws[32][96];    // [k][col]
    int tx = threadIdx.x;           // 0..15 -> cols tx*6..tx*6+5
    int ty = threadIdx.y;           // 0..15 -> rows ty*8..ty*8+7
    int tid = ty * 16 + tx;
    int rowBase = blockIdx.x * 128;

    // acc2[i][p] = packed {col tx*6+2p, col tx*6+2p+1} for row ty*8+i
    unsigned long long acc2[8][3] = {};

    for (int kt = 0; kt < K; kt += 32) {
        // X tile: 128 rows x 8 float4 along K (transposed into Xs)
        for (int idx = tid; idx < 128 * 8; idx += 256) {
            int row = idx >> 3;
            int kc  = idx & 7;
            int gr = rowBase + row;
            if (gr >= N_NODES) gr = N_NODES - 1;
            float4 v = *reinterpret_cast<const float4*>(X + (size_t)gr * K + kt + kc * 4);
            Xs[kc * 4 + 0][row] = v.x;
            Xs[kc * 4 + 1][row] = v.y;
            Xs[kc * 4 + 2][row] = v.z;
            Xs[kc * 4 + 3][row] = v.w;
        }
        // W tile: 32 x 96
        for (int idx = tid; idx < 32 * 24; idx += 256) {
            int kk = idx / 24;
            int cc = idx % 24;
            *reinterpret_cast<float4*>(&Ws[kk][cc * 4]) =
                *reinterpret_cast<const float4*>(W + (size_t)(kt + kk) * NHID + cc * 4);
        }
        __syncthreads();

#pragma unroll
        for (int k = 0; k < 32; k++) {
            float xr[8];
            *reinterpret_cast<float4*>(&xr[0]) = *reinterpret_cast<float4*>(&Xs[k][ty * 8]);
            *reinterpret_cast<float4*>(&xr[4]) = *reinterpret_cast<float4*>(&Xs[k][ty * 8 + 4]);
            // 6 weight cols as 3 packed f32x2 (8B-aligned: byte offset 24*tx)
            unsigned long long wc2[3];
            wc2[0] = *reinterpret_cast<unsigned long long*>(&Ws[k][tx * 6]);
            wc2[1] = *reinterpret_cast<unsigned long long*>(&Ws[k][tx * 6 + 2]);
            wc2[2] = *reinterpret_cast<unsigned long long*>(&Ws[k][tx * 6 + 4]);
#pragma unroll
            for (int i = 0; i < 8; i++) {
                unsigned int xb = __float_as_uint(xr[i]);
                unsigned long long xs;
                asm("mov.b64 %0, {%1, %1};" : "=l"(xs) : "r"(xb));
#pragma unroll
                for (int p = 0; p < 3; p++)
                    asm("fma.rn.f32x2 %0, %1, %2, %0;"
                        : "+l"(acc2[i][p]) : "l"(xs), "l"(wc2[p]));
            }
        }
        __syncthreads();
    }

#pragma unroll
    for (int i = 0; i < 8; i++) {
        int gr = rowBase + ty * 8 + i;
        if (gr < N_NODES) {
            // each acc2[i][p] is {even, odd} col pair in memory order
            unsigned long long* o =
                reinterpret_cast<unsigned long long*>(g_h + (size_t)gr * NHID + tx * 6);
            o[0] = acc2[i][0];
            o[1] = acc2[i][1];
            o[2] = acc2[i][2];
        }
    }
}

// ===========================================================================
// Aggregation core: warp accumulates weighted rows of g_h for one node.
// 8-edge groups; tail done as one predicated 8-wide group (w=0 lanes).
// ===========================================================================
__device__ __forceinline__ void agg8(const int2* __restrict__ eb, int j, int cnt,
                                     bool full, int lane,
                                     float& a0, float& a1, float& a2) {
    int   srcs[8];
    float ws[8];
#pragma unroll
    for (int k = 0; k < 8; k++) {
        bool ok = full || (j + k < cnt);
        int2 e = ok ? __ldg(&eb[j + k]) : make_int2(0, 0);
        srcs[k] = e.x;
        ws[k]   = ok ? __int_as_float(e.y) : 0.f;
    }
    float v0[8], v1[8], v2[8];
#pragma unroll
    for (int k = 0; k < 8; k++) {
        const float* h = g_h + (size_t)srcs[k] * NHID;
        v0[k] = __ldg(h + lane);
        v1[k] = __ldg(h + lane + 32);
        v2[k] = __ldg(h + lane + 64);
    }
#pragma unroll
    for (int k = 0; k < 8; k++) {
        a0 += ws[k] * v0[k];
        a1 += ws[k] * v1[k];
        a2 += ws[k] * v2[k];
    }
}

__device__ __forceinline__ void agg_rows(int node, int lane,
                                         float& a0, float& a1, float& a2) {
    int beg = __ldg(&g_rowbeg[node]);
    int cnt = __ldg(&g_cnt[node]);
    const int2* eb = g_edges + beg;
    int nfull = cnt & ~7;
    for (int j = 0; j < nfull; j += 8)
        agg8(eb, j, cnt, true, lane, a0, a1, a2);
    if (cnt & 7)
        agg8(eb, nfull, cnt, false, lane, a0, a1, a2);
}

// Aggregation + bias + L2-normalize + ReLU. One warp per dst node.
__global__ void agg_kernel(const float* __restrict__ bias) {
    int gw   = (blockIdx.x * blockDim.x + threadIdx.x) >> 5;
    int lane = threadIdx.x & 31;
    if (gw >= N_NODES) return;

    float a0 = 0.f, a1 = 0.f, a2 = 0.f;
    agg_rows(gw, lane, a0, a1, a2);

    a0 += __ldg(bias + lane); a1 += __ldg(bias + lane + 32); a2 += __ldg(bias + lane + 64);
    float s = a0 * a0 + a1 * a1 + a2 * a2;
#pragma unroll
    for (int o = 16; o; o >>= 1) s += __shfl_xor_sync(0xFFFFFFFFu, s, o);
    float inv = 1.0f / fmaxf(sqrtf(s), 1e-12f);

    float* row = g_a + (size_t)gw * NHID;
    row[lane]      = fmaxf(a0 * inv, 0.f);
    row[lane + 32] = fmaxf(a1 * inv, 0.f);
    row[lane + 64] = fmaxf(a2 * inv, 0.f);
}

// ===========================================================================
// Layer 3 fused head: agg + bias + norm + relu + emb + logits + softmax.
// ===========================================================================
__global__ void agg_head_kernel(const float* __restrict__ bias,
                                const float* __restrict__ linW,
                                const float* __restrict__ linb,
                                float* __restrict__ out) {
    __shared__ float Ws[NHID * NCLASS];
    __shared__ float bs[NCLASS];
    __shared__ float esh[8][NHID];

    int tid = threadIdx.x;
    for (int i = tid; i < NHID * NCLASS; i += 256) Ws[i] = linW[i];
    if (tid < NCLASS) bs[tid] = linb[tid];
    __syncthreads();

    int wid  = tid >> 5;
    int lane = tid & 31;
    int node = blockIdx.x * 8 + wid;
    if (node >= N_NODES) return;

    float a0 = 0.f, a1 = 0.f, a2 = 0.f;
    agg_rows(node, lane, a0, a1, a2);

    a0 += __ldg(bias + lane); a1 += __ldg(bias + lane + 32); a2 += __ldg(bias + lane + 64);
    float s = a0 * a0 + a1 * a1 + a2 * a2;
#pragma unroll
    for (int o = 16; o; o >>= 1) s += __shfl_xor_sync(0xFFFFFFFFu, s, o);
    float inv = 1.0f / fmaxf(sqrtf(s), 1e-12f);
    float e0 = fmaxf(a0 * inv, 0.f);
    float e1 = fmaxf(a1 * inv, 0.f);
    float e2 = fmaxf(a2 * inv, 0.f);

    const size_t EMB_OFF = 0;
    const size_t LOG_OFF = (size_t)N_NODES * NHID;
    const size_t PRB_OFF = LOG_OFF + (size_t)N_NODES * NCLASS;

    out[EMB_OFF + (size_t)node * NHID + lane]      = e0;
    out[EMB_OFF + (size_t)node * NHID + lane + 32] = e1;
    out[EMB_OFF + (size_t)node * NHID + lane + 64] = e2;
    esh[wid][lane] = e0; esh[wid][lane + 32] = e1; esh[wid][lane + 64] = e2;
    __syncwarp();

    float l0 = -INFINITY, l1 = -INFINITY;
    if (lane < NCLASS) {
        float a = bs[lane];
#pragma unroll
        for (int k = 0; k < NHID; k++) a += esh[wid][k] * Ws[k * NCLASS + lane];
        l0 = a;
    }
    if (lane < NCLASS - 32) {
        float a = bs[lane + 32];
#pragma unroll
        for (int k = 0; k < NHID; k++) a += esh[wid][k] * Ws[k * NCLASS + lane + 32];
        l1 = a;
    }

    float m = fmaxf(l0, l1);
#pragma unroll
    for (int o = 16; o; o >>= 1) m = fmaxf(m, __shfl_xor_sync(0xFFFFFFFFu, m, o));
    float sum = 0.f, p0 = 0.f, p1 = 0.f;
    if (lane < NCLASS)      { p0 = expf(l0 - m); sum += p0; }
    if (lane < NCLASS - 32) { p1 = expf(l1 - m); sum += p1; }
#pragma unroll
    for (int o = 16; o; o >>= 1) sum += __shfl_xor_sync(0xFFFFFFFFu, sum, o);
    float invs = 1.0f / sum;

    if (lane < NCLASS) {
        out[LOG_OFF + (size_t)node * NCLASS + lane] = l0;
        out[PRB_OFF + (size_t)node * NCLASS + lane] = p0 * invs;
    }
    if (lane < NCLASS - 32) {
        out[LOG_OFF + (size_t)node * NCLASS + lane + 32] = l1;
        out[PRB_OFF + (size_t)node * NCLASS + lane + 32] = p1 * invs;
    }
}

// ===========================================================================
extern "C" void kernel_launch(void* const* d_in, const int* in_sizes, int n_in,
                              void* d_out, int out_size) {
    const float* x    = (const float*)d_in[0];
    const int*   ei   = (const int*)d_in[1];
    const float* ew   = (const float*)d_in[2];
    const float* W1   = (const float*)d_in[3];
    const float* b1   = (const float*)d_in[4];
    const float* W2   = (const float*)d_in[5];
    const float* b2   = (const float*)d_in[6];
    const float* W3   = (const float*)d_in[7];
    const float* b3   = (const float*)d_in[8];
    const float* linW = (const float*)d_in[9];
    const float* linb = (const float*)d_in[10];
    float* out = (float*)d_out;

    const int* src = ei;
    const int* dst = ei + N_EDGES;

    void* pa = nullptr;
    cudaGetSymbolAddress(&pa, g_a);
    const float* xa = (const float*)pa;

    const int EDGE_GRID = (N_EDGES + 255) / 256;      // 3125
    const int GEMM_GRID = (N_NODES + 127) / 128;      // 391
    const int AGG_GRID  = (N_NODES * 32 + 255) / 256; // warp/node, 6250
    dim3 gblk(16, 16);

    // ---- CSR build, layer-1 GEMM kept in slot 3 (profiled) ----
    zero_cnt_kernel<<<NODE_BLKS, 256>>>();                 // slot 0
    hist_kernel<<<EDGE_GRID, 256>>>(dst);                  // slot 1
    scan_claim_kernel<<<NODE_BLKS, 256>>>();               // slot 2
    gemm_kernel<NFEAT><<<GEMM_GRID, gblk>>>(x, W1);        // slot 3 (profiled)
    place_kernel<<<EDGE_GRID, 256>>>(src, dst, ew);        // slot 4

    // ---- Layer 1 aggregation ----
    agg_kernel<<<AGG_GRID, 256>>>(b1);
    // ---- Layer 2 ----
    gemm_kernel<NHID><<<GEMM_GRID, gblk>>>(xa, W2);
    agg_kernel<<<AGG_GRID, 256>>>(b2);
    // ---- Layer 3 + head ----
    gemm_kernel<NHID><<<GEMM_GRID, gblk>>>(xa, W3);
    agg_head_kernel<<<(N_NODES + 7) / 8, 256>>>(b3, linW, linb, out);
}